// round 1
// baseline (speedup 1.0000x reference)
#include <cuda_runtime.h>
#include <math.h>

#define NN 8192
#define CC 128
#define TT 256
#define PD 384   // TT + OUT
#define OUTD 128
#define MAXD 192 // max row degree (mean ~82, sd ~9 -> 192 is >10 sigma)

// ---------------- scratch (static device globals; no allocations) ----------
__device__ float g_pS[64 * CC];
__device__ float g_pQ[64 * CC];
__device__ float g_s[CC];
__device__ float g_t[CC];
__device__ float g_P[(size_t)NN * PD];       // [Hx | HW] rows, 12 MB (fits L2)
__device__ int   g_cols[(size_t)NN * MAXD];  // per-row neighbor columns
__device__ int   g_deg[NN];

// ---------------- BatchNorm statistics ------------------------------------
__global__ void bn_partial(const float* __restrict__ H) {
    int b = blockIdx.x, c = threadIdx.x;            // 64 blocks x 128 threads
    const float* p = H + (size_t)b * 128 * CC + c;
    float s = 0.f, q = 0.f;
#pragma unroll 4
    for (int r = 0; r < 128; r++) {
        float h = p[(size_t)r * CC];
        s += h; q += h * h;
    }
    g_pS[b * CC + c] = s;
    g_pQ[b * CC + c] = q;
}

__global__ void bn_final(const float* __restrict__ gamma,
                         const float* __restrict__ beta) {
    int c = threadIdx.x;
    float s = 0.f, q = 0.f;
    for (int b = 0; b < 64; b++) { s += g_pS[b * CC + c]; q += g_pQ[b * CC + c]; }
    float mu  = s / (float)NN;
    float var = q / (float)NN - mu * mu;           // biased variance (matches jnp.var)
    float r   = rsqrtf(var + 1e-5f);
    float sc  = r * gamma[c];
    g_s[c] = sc;
    g_t[c] = beta[c] - mu * sc;
}

// ---------------- projection GEMM: P = BN(H) @ [W1|Wo] + [b1|bo] ----------
__global__ void gemm_proj(const float* __restrict__ H,
                          const float* __restrict__ W1,
                          const float* __restrict__ b1,
                          const float* __restrict__ Wo,
                          const float* __restrict__ bo) {
    __shared__ float As[32][65];  // [k][row], padded
    __shared__ float Bs[32][64];  // [k][col]
    int tid = threadIdx.x;
    int tx = tid & 15, ty = tid >> 4;
    int m0 = blockIdx.y * 64, n0 = blockIdx.x * 64;
    float acc[4][4] = {};

    for (int k0 = 0; k0 < CC; k0 += 32) {
        // A tile with BN folded in
        {
            int kk = tid & 31, r = tid >> 5;
            float sc = g_s[k0 + kk], tt = g_t[k0 + kk];
#pragma unroll
            for (int rr = 0; rr < 64; rr += 8) {
                float h = H[(size_t)(m0 + r + rr) * CC + k0 + kk];
                As[kk][r + rr] = h * sc + tt;
            }
        }
        // B tile (virtual concat of W1 | Wo)
        {
            int n = tid & 63, kb = tid >> 6;
#pragma unroll
            for (int kq = 0; kq < 32; kq += 4) {
                int k = k0 + kq + kb;
                int gn = n0 + n;
                float v = (gn < TT) ? W1[(size_t)k * TT + gn]
                                    : Wo[(size_t)k * CC + (gn - TT)];
                Bs[kq + kb][n] = v;
            }
        }
        __syncthreads();
#pragma unroll
        for (int kk = 0; kk < 32; kk++) {
            float a[4], bb[4];
#pragma unroll
            for (int i = 0; i < 4; i++) a[i] = As[kk][ty * 4 + i];
#pragma unroll
            for (int j = 0; j < 4; j++) bb[j] = Bs[kk][tx * 4 + j];
#pragma unroll
            for (int i = 0; i < 4; i++)
#pragma unroll
                for (int j = 0; j < 4; j++) acc[i][j] += a[i] * bb[j];
        }
        __syncthreads();
    }
#pragma unroll
    for (int i = 0; i < 4; i++) {
        int row = m0 + ty * 4 + i;
#pragma unroll
        for (int j = 0; j < 4; j++) {
            int gn = n0 + tx * 4 + j;
            float bias = (gn < TT) ? b1[gn] : bo[gn - TT];
            g_P[(size_t)row * PD + gn] = acc[i][j] + bias;
        }
    }
}

// ---------------- adjacency structure: warp-per-row ordered compaction ----
__global__ void build_adj(const float* __restrict__ A) {
    int warp = threadIdx.x >> 5, lane = threadIdx.x & 31;
    int r = blockIdx.x * 8 + warp;
    const float4* row = (const float4*)(A + (size_t)r * NN);
    int* cols = g_cols + (size_t)r * MAXD;
    int base = 0;
#pragma unroll 1
    for (int it = 0; it < NN / 128; it++) {       // 64 iters, 128 cols each
        float4 v = row[it * 32 + lane];
        int m0 = v.x != 0.f, m1 = v.y != 0.f, m2 = v.z != 0.f, m3 = v.w != 0.f;
        int cnt = m0 + m1 + m2 + m3;
        int off = cnt;
#pragma unroll
        for (int d = 1; d < 32; d <<= 1) {
            int n = __shfl_up_sync(0xFFFFFFFFu, off, d);
            if (lane >= d) off += n;
        }
        int total = __shfl_sync(0xFFFFFFFFu, off, 31);
        int pos = base + off - cnt;
        int col = it * 128 + lane * 4;
        if (m0) { if (pos < MAXD) cols[pos] = col;     pos++; }
        if (m1) { if (pos < MAXD) cols[pos] = col + 1; pos++; }
        if (m2) { if (pos < MAXD) cols[pos] = col + 2; pos++; }
        if (m3) { if (pos < MAXD) cols[pos] = col + 3; pos++; }
        base += total;
    }
    if (lane == 0) g_deg[r] = base < MAXD ? base : MAXD;
}

// ---------------- fused: SDDMM + sigmoid + 2x softmax + scatter + SpMM ----
__global__ __launch_bounds__(256)
void fused_row(float* __restrict__ outY, float* __restrict__ outA) {
    int i = blockIdx.x;
    __shared__ float sHx[TT];
    __shared__ int   sCols[MAXD];
    __shared__ float sV[MAXD];
    __shared__ float sW1[MAXD];
    __shared__ float sW2[MAXD];
    __shared__ float red1[256];
    __shared__ float red2[256];

    int tid = threadIdx.x;
    int deg = g_deg[i];
    if (tid < deg) sCols[tid] = g_cols[(size_t)i * MAXD + tid];
    sHx[tid] = g_P[(size_t)i * PD + tid];      // tid < 256 == TT
    __syncthreads();

    // SDDMM: dot(Hx[i], Hx[j]) -> sigmoid
    int warp = tid >> 5, lane = tid & 31;
    for (int k = warp; k < deg; k += 8) {
        const float* hj = g_P + (size_t)sCols[k] * PD;
        float p = 0.f;
#pragma unroll
        for (int e = 0; e < 8; e++) {
            int idx = lane + e * 32;
            p += sHx[idx] * hj[idx];
        }
#pragma unroll
        for (int d = 16; d; d >>= 1) p += __shfl_xor_sync(0xFFFFFFFFu, p, d);
        if (lane == 0) sV[k] = 1.f / (1.f + expf(-p));
    }
    __syncthreads();

    // dual softmax over the sparse set (logits in (0,2], no max-shift needed;
    // masked entries are exactly 0 in the reference too)
    float E1 = 0.f, E2 = 0.f;
    if (tid < deg) {
        float v = sV[tid];
        float l1 = v + (sCols[tid] == i ? 1.f : 0.f);  // +eye on diagonal
        E1 = expf(l1);
        E2 = expf(v);
        sW1[tid] = E1; sW2[tid] = E2;
    }
    red1[tid] = E1; red2[tid] = E2;
    __syncthreads();
#pragma unroll
    for (int s = 128; s; s >>= 1) {
        if (tid < s) { red1[tid] += red1[tid + s]; red2[tid] += red2[tid + s]; }
        __syncthreads();
    }
    float inv1 = 1.f / red1[0], inv2 = 1.f / red2[0];
    if (tid < deg) {
        float w1 = sW1[tid] * inv1, w2 = sW2[tid] * inv2;
        sW1[tid] = w1; sW2[tid] = w2;
        if (outA) outA[(size_t)i * NN + sCols[tid]] = w1;  // scatter A_soft
    }
    __syncthreads();

    // SpMM rows: y1 = A_soft @ HW, y2 = A1_soft @ HW ; out = leaky(y1)+leaky(y2)
    if (tid < OUTD) {
        float a1 = 0.f, a2 = 0.f;
#pragma unroll 4
        for (int k = 0; k < deg; k++) {
            float h = g_P[(size_t)sCols[k] * PD + TT + tid];
            a1 += sW1[k] * h;
            a2 += sW2[k] * h;
        }
        float o1 = a1 >= 0.f ? a1 : 0.01f * a1;
        float o2 = a2 >= 0.f ? a2 : 0.01f * a2;
        outY[(size_t)i * OUTD + tid] = o1 + o2;
    }
}

// ---------------- launch ---------------------------------------------------
extern "C" void kernel_launch(void* const* d_in, const int* in_sizes, int n_in,
                              void* d_out, int out_size) {
    const float* H     = (const float*)d_in[0];
    const float* A     = (const float*)d_in[1];
    const float* gamma = (const float*)d_in[2];
    const float* beta  = (const float*)d_in[3];
    const float* W1    = (const float*)d_in[4];
    const float* b1    = (const float*)d_in[5];
    const float* Wo    = (const float*)d_in[6];
    const float* bo    = (const float*)d_in[7];

    float* outY = (float*)d_out;
    float* outA = nullptr;
    if ((long long)out_size >= (long long)NN * OUTD + (long long)NN * NN)
        outA = (float*)d_out + (size_t)NN * OUTD;

    bn_partial<<<64, 128>>>(H);
    bn_final<<<1, 128>>>(gamma, beta);
    gemm_proj<<<dim3(6, 128), 256>>>(H, W1, b1, Wo, bo);
    build_adj<<<1024, 256>>>(A);
    if (outA)
        cudaMemsetAsync(outA, 0, (size_t)NN * NN * sizeof(float));
    fused_row<<<NN, 256>>>(outY, outA);
}

// round 2
// speedup vs baseline: 1.1012x; 1.1012x over previous
#include <cuda_runtime.h>
#include <math.h>

#define NN 8192
#define CC 128
#define TT 256
#define PD 384   // TT + OUT
#define OUTD 128
#define MAXD 144 // max row degree (Binomial(8192,0.01): mean 82, max ~116; 144 safe)

// ---------------- scratch (static device globals; no allocations) ----------
__device__ float g_pS[64 * CC];
__device__ float g_pQ[64 * CC];
__device__ float g_s[CC];
__device__ float g_t[CC];
__device__ float g_P[(size_t)NN * PD];       // [Hx | HW] rows, 12.6 MB (fits L2)

// ---------------- BatchNorm statistics ------------------------------------
__global__ void bn_partial(const float* __restrict__ H) {
    int b = blockIdx.x, c = threadIdx.x;            // 64 blocks x 128 threads
    const float* p = H + (size_t)b * 128 * CC + c;
    float s = 0.f, q = 0.f;
#pragma unroll 4
    for (int r = 0; r < 128; r++) {
        float h = p[(size_t)r * CC];
        s += h; q += h * h;
    }
    g_pS[b * CC + c] = s;
    g_pQ[b * CC + c] = q;
}

__global__ void bn_final(const float* __restrict__ gamma,
                         const float* __restrict__ beta) {
    int c = threadIdx.x;
    float s = 0.f, q = 0.f;
    for (int b = 0; b < 64; b++) { s += g_pS[b * CC + c]; q += g_pQ[b * CC + c]; }
    float mu  = s / (float)NN;
    float var = q / (float)NN - mu * mu;           // biased variance (matches jnp.var)
    float r   = rsqrtf(var + 1e-5f);
    float sc  = r * gamma[c];
    g_s[c] = sc;
    g_t[c] = beta[c] - mu * sc;
}

// ---------------- projection GEMM: P = BN(H) @ [W1|Wo] + [b1|bo] ----------
__global__ void gemm_proj(const float* __restrict__ H,
                          const float* __restrict__ W1,
                          const float* __restrict__ b1,
                          const float* __restrict__ Wo,
                          const float* __restrict__ bo) {
    __shared__ float As[32][65];  // [k][row], padded
    __shared__ float Bs[32][64];  // [k][col]
    int tid = threadIdx.x;
    int tx = tid & 15, ty = tid >> 4;
    int m0 = blockIdx.y * 64, n0 = blockIdx.x * 64;
    float acc[4][4] = {};

    for (int k0 = 0; k0 < CC; k0 += 32) {
        {
            int kk = tid & 31, r = tid >> 5;
            float sc = g_s[k0 + kk], tt = g_t[k0 + kk];
#pragma unroll
            for (int rr = 0; rr < 64; rr += 8) {
                float h = H[(size_t)(m0 + r + rr) * CC + k0 + kk];
                As[kk][r + rr] = h * sc + tt;
            }
        }
        {
            int n = tid & 63, kb = tid >> 6;
#pragma unroll
            for (int kq = 0; kq < 32; kq += 4) {
                int k = k0 + kq + kb;
                int gn = n0 + n;
                float v = (gn < TT) ? W1[(size_t)k * TT + gn]
                                    : Wo[(size_t)k * CC + (gn - TT)];
                Bs[kq + kb][n] = v;
            }
        }
        __syncthreads();
#pragma unroll
        for (int kk = 0; kk < 32; kk++) {
            float a[4], bb[4];
#pragma unroll
            for (int i = 0; i < 4; i++) a[i] = As[kk][ty * 4 + i];
#pragma unroll
            for (int j = 0; j < 4; j++) bb[j] = Bs[kk][tx * 4 + j];
#pragma unroll
            for (int i = 0; i < 4; i++)
#pragma unroll
                for (int j = 0; j < 4; j++) acc[i][j] += a[i] * bb[j];
        }
        __syncthreads();
    }
#pragma unroll
    for (int i = 0; i < 4; i++) {
        int row = m0 + ty * 4 + i;
#pragma unroll
        for (int j = 0; j < 4; j++) {
            int gn = n0 + tx * 4 + j;
            float bias = (gn < TT) ? b1[gn] : bo[gn - TT];
            g_P[(size_t)row * PD + gn] = acc[i][j] + bias;
        }
    }
}

// ---- mega-fused: zero-write + compaction + SDDMM + softmax + scatter + SpMM
__global__ __launch_bounds__(256)
void mega_row(const float* __restrict__ A,
              float* __restrict__ outY, float* __restrict__ outA) {
    int i = blockIdx.x;
    __shared__ float sHx[TT];
    __shared__ int   sCols[MAXD];
    __shared__ float sV[MAXD];
    __shared__ float sW1[MAXD];
    __shared__ float sW2[MAXD];
    __shared__ float red1[256];
    __shared__ float red2[256];
    __shared__ float acc1[128];
    __shared__ float acc2[128];
    __shared__ int   sCnt;

    int tid = threadIdx.x, warp = tid >> 5, lane = tid & 31;

    // (1) zero-write this row of dense A_soft FIRST — pure DRAM-write traffic,
    //     fire-and-forget, overlaps with everything below.
    if (outA) {
        float4 z = make_float4(0.f, 0.f, 0.f, 0.f);
        float4* dst = (float4*)(outA + (size_t)i * NN);
#pragma unroll
        for (int c = 0; c < 8; c++) dst[tid + c * 256] = z;
    }

    if (tid == 0) sCnt = 0;
    sHx[tid] = g_P[(size_t)i * PD + tid];      // tid < 256 == TT
    __syncthreads();

    // (2) compact A row via ballots: warp w owns cols [w*1024, (w+1)*1024)
    const float4* row = (const float4*)(A + (size_t)i * NN);
#pragma unroll 1
    for (int c = 0; c < 8; c++) {
        float4 v = row[warp * 256 + c * 32 + lane];
        unsigned b0 = __ballot_sync(0xFFFFFFFFu, v.x != 0.f);
        unsigned b1 = __ballot_sync(0xFFFFFFFFu, v.y != 0.f);
        unsigned b2 = __ballot_sync(0xFFFFFFFFu, v.z != 0.f);
        unsigned b3 = __ballot_sync(0xFFFFFFFFu, v.w != 0.f);
        int total = __popc(b0) + __popc(b1) + __popc(b2) + __popc(b3);
        int base = 0;
        if (lane == 0 && total) base = atomicAdd(&sCnt, total);
        base = __shfl_sync(0xFFFFFFFFu, base, 0);
        unsigned lt = (1u << lane) - 1u;
        int col = warp * 1024 + c * 128 + lane * 4;
        int p;
        if (v.x != 0.f) { p = base + __popc(b0 & lt);
                          if (p < MAXD) sCols[p] = col; }
        if (v.y != 0.f) { p = base + __popc(b0) + __popc(b1 & lt);
                          if (p < MAXD) sCols[p] = col + 1; }
        if (v.z != 0.f) { p = base + __popc(b0) + __popc(b1) + __popc(b2 & lt);
                          if (p < MAXD) sCols[p] = col + 2; }
        if (v.w != 0.f) { p = base + __popc(b0) + __popc(b1) + __popc(b2) + __popc(b3 & lt);
                          if (p < MAXD) sCols[p] = col + 3; }
    }
    __syncthreads();
    int deg = min(sCnt, MAXD);

    // (3) SDDMM: warp per edge, dot(Hx[i], Hx[j]) -> sigmoid
    const float4* sHx4 = (const float4*)sHx;
    for (int k = warp; k < deg; k += 8) {
        const float4* hj = (const float4*)(g_P + (size_t)sCols[k] * PD);
        float4 a = sHx4[lane],      b = hj[lane];
        float  p = a.x * b.x + a.y * b.y + a.z * b.z + a.w * b.w;
        float4 a2 = sHx4[lane + 32], b2 = hj[lane + 32];
        p += a2.x * b2.x + a2.y * b2.y + a2.z * b2.z + a2.w * b2.w;
#pragma unroll
        for (int d = 16; d; d >>= 1) p += __shfl_xor_sync(0xFFFFFFFFu, p, d);
        if (lane == 0) sV[k] = 1.f / (1.f + expf(-p));
    }
    __syncthreads();

    // (4) dual softmax over the sparse set (logits in (0,2], no max-shift)
    float E1 = 0.f, E2 = 0.f;
    if (tid < deg) {
        float v = sV[tid];
        float l1 = v + (sCols[tid] == i ? 1.f : 0.f);  // +eye on diagonal
        E1 = expf(l1);
        E2 = expf(v);
        sW1[tid] = E1; sW2[tid] = E2;
    }
    red1[tid] = E1; red2[tid] = E2;
    __syncthreads();
#pragma unroll
    for (int s = 128; s; s >>= 1) {
        if (tid < s) { red1[tid] += red1[tid + s]; red2[tid] += red2[tid + s]; }
        __syncthreads();
    }
    float inv1 = 1.f / red1[0], inv2 = 1.f / red2[0];
    if (tid < deg) {
        float w1 = sW1[tid] * inv1, w2 = sW2[tid] * inv2;
        sW1[tid] = w1; sW2[tid] = w2;
        // scatter A_soft nonzeros (ordered after the zero writes by the
        // __syncthreads barriers above)
        if (outA) outA[(size_t)i * NN + sCols[tid]] = w1;
    }
    __syncthreads();

    // (5) SpMM: all 256 threads, 2-way split over edges per output dim
    {
        int d   = tid & 127;
        int par = tid >> 7;
        float a1 = 0.f, a2 = 0.f;
#pragma unroll 2
        for (int k = par; k < deg; k += 2) {
            float h = g_P[(size_t)sCols[k] * PD + TT + d];
            a1 += sW1[k] * h;
            a2 += sW2[k] * h;
        }
        if (par) { acc1[d] = a1; acc2[d] = a2; }
        __syncthreads();
        if (!par) {
            a1 += acc1[d]; a2 += acc2[d];
            float o1 = a1 >= 0.f ? a1 : 0.01f * a1;
            float o2 = a2 >= 0.f ? a2 : 0.01f * a2;
            outY[(size_t)i * OUTD + d] = o1 + o2;
        }
    }
}

// ---------------- launch ---------------------------------------------------
extern "C" void kernel_launch(void* const* d_in, const int* in_sizes, int n_in,
                              void* d_out, int out_size) {
    const float* H     = (const float*)d_in[0];
    const float* A     = (const float*)d_in[1];
    const float* gamma = (const float*)d_in[2];
    const float* beta  = (const float*)d_in[3];
    const float* W1    = (const float*)d_in[4];
    const float* b1    = (const float*)d_in[5];
    const float* Wo    = (const float*)d_in[6];
    const float* bo    = (const float*)d_in[7];

    float* outY = (float*)d_out;
    float* outA = nullptr;
    if ((long long)out_size >= (long long)NN * OUTD + (long long)NN * NN)
        outA = (float*)d_out + (size_t)NN * OUTD;

    bn_partial<<<64, 128>>>(H);
    bn_final<<<1, 128>>>(gamma, beta);
    gemm_proj<<<dim3(6, 128), 256>>>(H, W1, b1, Wo, bo);
    mega_row<<<NN, 256>>>(A, outY, outA);
}

// round 3
// speedup vs baseline: 1.1528x; 1.0468x over previous
#include <cuda_runtime.h>
#include <math.h>

#define NN 8192
#define CC 128
#define TT 256
#define PD 384   // TT + OUT
#define OUTD 128
#define MAXD 144 // max row degree (Binomial(8192,0.01): mean 82, max ~116; 144 safe)

// ---------------- scratch (static device globals; no allocations) ----------
__device__ float g_pS[256 * CC];
__device__ float g_pQ[256 * CC];
__device__ float g_s[CC];
__device__ float g_t[CC];
__device__ float g_P[(size_t)NN * PD];       // [Hx | HW] rows, 12.6 MB (fits L2)

// ---------------- BatchNorm statistics ------------------------------------
__global__ void bn_partial(const float* __restrict__ H) {
    int b = blockIdx.x, c = threadIdx.x;            // 256 blocks x 128 threads
    const float* p = H + (size_t)b * 32 * CC + c;
    float s = 0.f, q = 0.f;
#pragma unroll 8
    for (int r = 0; r < 32; r++) {
        float h = p[(size_t)r * CC];
        s += h; q += h * h;
    }
    g_pS[b * CC + c] = s;
    g_pQ[b * CC + c] = q;
}

__global__ void bn_final(const float* __restrict__ gamma,
                         const float* __restrict__ beta) {
    int c = threadIdx.x;
    float s = 0.f, q = 0.f;
#pragma unroll 8
    for (int b = 0; b < 256; b++) { s += g_pS[b * CC + c]; q += g_pQ[b * CC + c]; }
    float mu  = s / (float)NN;
    float var = q / (float)NN - mu * mu;           // biased variance (matches jnp.var)
    float r   = rsqrtf(var + 1e-5f);
    float sc  = r * gamma[c];
    g_s[c] = sc;
    g_t[c] = beta[c] - mu * sc;
}

// ---------------- projection GEMM: P = BN(H) @ [W1|Wo] + [b1|bo] ----------
__global__ void gemm_proj(const float* __restrict__ H,
                          const float* __restrict__ W1,
                          const float* __restrict__ b1,
                          const float* __restrict__ Wo,
                          const float* __restrict__ bo) {
    __shared__ float As[32][65];  // [k][row], padded
    __shared__ float Bs[32][64];  // [k][col]
    int tid = threadIdx.x;
    int tx = tid & 15, ty = tid >> 4;
    int m0 = blockIdx.y * 64, n0 = blockIdx.x * 64;
    float acc[4][4] = {};

    for (int k0 = 0; k0 < CC; k0 += 32) {
        {
            int kk = tid & 31, r = tid >> 5;
            float sc = g_s[k0 + kk], tt = g_t[k0 + kk];
#pragma unroll
            for (int rr = 0; rr < 64; rr += 8) {
                float h = H[(size_t)(m0 + r + rr) * CC + k0 + kk];
                As[kk][r + rr] = h * sc + tt;
            }
        }
        {
            int n = tid & 63, kb = tid >> 6;
#pragma unroll
            for (int kq = 0; kq < 32; kq += 4) {
                int k = k0 + kq + kb;
                int gn = n0 + n;
                float v = (gn < TT) ? W1[(size_t)k * TT + gn]
                                    : Wo[(size_t)k * CC + (gn - TT)];
                Bs[kq + kb][n] = v;
            }
        }
        __syncthreads();
#pragma unroll
        for (int kk = 0; kk < 32; kk++) {
            float a[4], bb[4];
#pragma unroll
            for (int i = 0; i < 4; i++) a[i] = As[kk][ty * 4 + i];
#pragma unroll
            for (int j = 0; j < 4; j++) bb[j] = Bs[kk][tx * 4 + j];
#pragma unroll
            for (int i = 0; i < 4; i++)
#pragma unroll
                for (int j = 0; j < 4; j++) acc[i][j] += a[i] * bb[j];
        }
        __syncthreads();
    }
#pragma unroll
    for (int i = 0; i < 4; i++) {
        int row = m0 + ty * 4 + i;
#pragma unroll
        for (int j = 0; j < 4; j++) {
            int gn = n0 + tx * 4 + j;
            float bias = (gn < TT) ? b1[gn] : bo[gn - TT];
            g_P[(size_t)row * PD + gn] = acc[i][j] + bias;
        }
    }
}

// ---- mega-fused: zero-write + compaction + SDDMM + softmax + scatter + SpMM
__global__ __launch_bounds__(256)
void mega_row(const float* __restrict__ A,
              float* __restrict__ outY, float* __restrict__ outA) {
    int i = blockIdx.x;
    __shared__ float  sHx[TT];
    __shared__ int    sCols[MAXD];
    __shared__ float  sV[MAXD];
    __shared__ float4 sEdge[MAXD];   // {w1, w2, g_P index bits, unused}
    __shared__ float  red[8];
    __shared__ float  acc1[128];
    __shared__ float  acc2[128];
    __shared__ float  sDelta, sInv1, sInv2;
    __shared__ int    sCnt;

    int tid = threadIdx.x, warp = tid >> 5, lane = tid & 31;

    // (1) zero-write this row of dense A_soft FIRST — DRAM-write traffic that
    //     overlaps with everything below.
    if (outA) {
        float4 z = make_float4(0.f, 0.f, 0.f, 0.f);
        float4* dst = (float4*)(outA + (size_t)i * NN);
#pragma unroll
        for (int c = 0; c < 8; c++) dst[tid + c * 256] = z;
    }

    if (tid == 0) { sCnt = 0; sDelta = 0.f; }
    sHx[tid] = g_P[(size_t)i * PD + tid];      // tid < 256 == TT
    __syncthreads();

    // (2) compact A row via ballots: warp w owns cols [w*1024, (w+1)*1024)
    const float4* row = (const float4*)(A + (size_t)i * NN);
#pragma unroll 1
    for (int c = 0; c < 8; c++) {
        float4 v = row[warp * 256 + c * 32 + lane];
        unsigned b0 = __ballot_sync(0xFFFFFFFFu, v.x != 0.f);
        unsigned b1 = __ballot_sync(0xFFFFFFFFu, v.y != 0.f);
        unsigned b2 = __ballot_sync(0xFFFFFFFFu, v.z != 0.f);
        unsigned b3 = __ballot_sync(0xFFFFFFFFu, v.w != 0.f);
        int total = __popc(b0) + __popc(b1) + __popc(b2) + __popc(b3);
        int base = 0;
        if (lane == 0 && total) base = atomicAdd(&sCnt, total);
        base = __shfl_sync(0xFFFFFFFFu, base, 0);
        unsigned lt = (1u << lane) - 1u;
        int col = warp * 1024 + c * 128 + lane * 4;
        int p;
        if (v.x != 0.f) { p = base + __popc(b0 & lt);
                          if (p < MAXD) sCols[p] = col; }
        if (v.y != 0.f) { p = base + __popc(b0) + __popc(b1 & lt);
                          if (p < MAXD) sCols[p] = col + 1; }
        if (v.z != 0.f) { p = base + __popc(b0) + __popc(b1) + __popc(b2 & lt);
                          if (p < MAXD) sCols[p] = col + 2; }
        if (v.w != 0.f) { p = base + __popc(b0) + __popc(b1) + __popc(b2) + __popc(b3 & lt);
                          if (p < MAXD) sCols[p] = col + 3; }
    }
    __syncthreads();
    int deg = min(sCnt, MAXD);

    // (3) SDDMM: warp per edge, dot(Hx[i], Hx[j]) -> sigmoid
    {
        const float4* sHx4 = (const float4*)sHx;
        float4 a0 = sHx4[lane];          // loop-invariant, lives in registers
        float4 a1 = sHx4[lane + 32];
        for (int k = warp; k < deg; k += 8) {
            const float4* hj = (const float4*)(g_P + (size_t)sCols[k] * PD);
            float4 b0 = hj[lane], b1 = hj[lane + 32];
            float p = a0.x * b0.x + a0.y * b0.y + a0.z * b0.z + a0.w * b0.w
                    + a1.x * b1.x + a1.y * b1.y + a1.z * b1.z + a1.w * b1.w;
#pragma unroll
            for (int d = 16; d; d >>= 1) p += __shfl_xor_sync(0xFFFFFFFFu, p, d);
            if (lane == 0) sV[k] = 1.f / (1.f + __expf(-p));
        }
    }
    __syncthreads();

    // (4) single softmax reduction: exp(v+1) = e*exp(v), so the two softmaxes
    //     share one exp and one sum (sum1 = sum2 + (e-1)*E_diag).
    float E = 0.f; int col = -1;
    if (tid < deg) {
        col = sCols[tid];
        E = __expf(sV[tid]);
        if (col == i) sDelta = 1.718281828459045f * E;   // at most one writer
    }
    {
        float s = E;
#pragma unroll
        for (int d = 16; d; d >>= 1) s += __shfl_xor_sync(0xFFFFFFFFu, s, d);
        if (lane == 0) red[warp] = s;
    }
    __syncthreads();
    if (tid == 0) {
        float sum2 = red[0] + red[1] + red[2] + red[3]
                   + red[4] + red[5] + red[6] + red[7];
        float sum1 = sum2 + sDelta;
        sInv1 = 1.f / sum1;
        sInv2 = 1.f / sum2;
    }
    __syncthreads();
    if (tid < deg) {
        float inv1 = sInv1, inv2 = sInv2;
        float E1 = (col == i) ? 2.718281828459045f * E : E;
        float w1 = E1 * inv1;
        float w2 = E  * inv2;
        sEdge[tid] = make_float4(w1, w2, __int_as_float(col * PD + TT), 0.f);
        if (outA) outA[(size_t)i * NN + col] = w1;   // scatter A_soft
    }
    __syncthreads();

    // (5) SpMM: 256 threads = 2 edge-partitions x 128 dims; one LDS128/edge
    {
        int d   = tid & 127;
        int par = tid >> 7;
        float a1 = 0.f, a2 = 0.f;
#pragma unroll 2
        for (int k = par; k < deg; k += 2) {
            float4 ed = sEdge[k];
            float h = g_P[__float_as_int(ed.z) + d];
            a1 += ed.x * h;
            a2 += ed.y * h;
        }
        if (par) { acc1[d] = a1; acc2[d] = a2; }
        __syncthreads();
        if (!par) {
            a1 += acc1[d]; a2 += acc2[d];
            float o1 = a1 >= 0.f ? a1 : 0.01f * a1;
            float o2 = a2 >= 0.f ? a2 : 0.01f * a2;
            outY[(size_t)i * OUTD + d] = o1 + o2;
        }
    }
}

// ---------------- launch ---------------------------------------------------
extern "C" void kernel_launch(void* const* d_in, const int* in_sizes, int n_in,
                              void* d_out, int out_size) {
    const float* H     = (const float*)d_in[0];
    const float* A     = (const float*)d_in[1];
    const float* gamma = (const float*)d_in[2];
    const float* beta  = (const float*)d_in[3];
    const float* W1    = (const float*)d_in[4];
    const float* b1    = (const float*)d_in[5];
    const float* Wo    = (const float*)d_in[6];
    const float* bo    = (const float*)d_in[7];

    float* outY = (float*)d_out;
    float* outA = nullptr;
    if ((long long)out_size >= (long long)NN * OUTD + (long long)NN * NN)
        outA = (float*)d_out + (size_t)NN * OUTD;

    bn_partial<<<256, 128>>>(H);
    bn_final<<<1, 128>>>(gamma, beta);
    gemm_proj<<<dim3(6, 128), 256>>>(H, W1, b1, Wo, bo);
    mega_row<<<NN, 256>>>(A, outY, outA);
}

// round 4
// speedup vs baseline: 1.2055x; 1.0457x over previous
#include <cuda_runtime.h>
#include <math.h>

#define NN 8192
#define CC 128
#define TT 256
#define PD 384   // TT + OUT
#define OUTD 128
#define MAXD 144 // max row degree (Binomial(8192,0.01): mean 82, max ~116; 144 safe)

// ---------------- scratch (static device globals; no allocations) ----------
__device__ float g_pS[256 * CC];
__device__ float g_pQ[256 * CC];
__device__ float g_s[CC];
__device__ float g_t[CC];
__device__ float g_P[(size_t)NN * PD];       // [Hx | HW] rows, 12.6 MB (fits L2)

// ---------------- BatchNorm statistics ------------------------------------
__global__ void bn_partial(const float* __restrict__ H) {
    int b = blockIdx.x, c = threadIdx.x;            // 256 blocks x 128 threads
    const float* p = H + (size_t)b * 32 * CC + c;
    float s = 0.f, q = 0.f;
#pragma unroll 8
    for (int r = 0; r < 32; r++) {
        float h = p[(size_t)r * CC];
        s += h; q += h * h;
    }
    g_pS[b * CC + c] = s;
    g_pQ[b * CC + c] = q;
}

__global__ void bn_final(const float* __restrict__ gamma,
                         const float* __restrict__ beta) {
    int c = threadIdx.x;
    float s = 0.f, q = 0.f;
#pragma unroll 8
    for (int b = 0; b < 256; b++) { s += g_pS[b * CC + c]; q += g_pQ[b * CC + c]; }
    float mu  = s / (float)NN;
    float var = q / (float)NN - mu * mu;           // biased variance (matches jnp.var)
    float r   = rsqrtf(var + 1e-5f);
    float sc  = r * gamma[c];
    g_s[c] = sc;
    g_t[c] = beta[c] - mu * sc;
}

// ---------------- projection GEMM: P = BN(H) @ [W1|Wo] + [b1|bo] ----------
__global__ void gemm_proj(const float* __restrict__ H,
                          const float* __restrict__ W1,
                          const float* __restrict__ b1,
                          const float* __restrict__ Wo,
                          const float* __restrict__ bo) {
    __shared__ float As[32][65];  // [k][row], padded
    __shared__ float Bs[32][64];  // [k][col]
    int tid = threadIdx.x;
    int tx = tid & 15, ty = tid >> 4;
    int m0 = blockIdx.y * 64, n0 = blockIdx.x * 64;
    float acc[4][4] = {};

    for (int k0 = 0; k0 < CC; k0 += 32) {
        {
            int kk = tid & 31, r = tid >> 5;
            float sc = g_s[k0 + kk], tt = g_t[k0 + kk];
#pragma unroll
            for (int rr = 0; rr < 64; rr += 8) {
                float h = H[(size_t)(m0 + r + rr) * CC + k0 + kk];
                As[kk][r + rr] = h * sc + tt;
            }
        }
        {
            int n = tid & 63, kb = tid >> 6;
#pragma unroll
            for (int kq = 0; kq < 32; kq += 4) {
                int k = k0 + kq + kb;
                int gn = n0 + n;
                float v = (gn < TT) ? W1[(size_t)k * TT + gn]
                                    : Wo[(size_t)k * CC + (gn - TT)];
                Bs[kq + kb][n] = v;
            }
        }
        __syncthreads();
#pragma unroll
        for (int kk = 0; kk < 32; kk++) {
            float a[4], bb[4];
#pragma unroll
            for (int i = 0; i < 4; i++) a[i] = As[kk][ty * 4 + i];
#pragma unroll
            for (int j = 0; j < 4; j++) bb[j] = Bs[kk][tx * 4 + j];
#pragma unroll
            for (int i = 0; i < 4; i++)
#pragma unroll
                for (int j = 0; j < 4; j++) acc[i][j] += a[i] * bb[j];
        }
        __syncthreads();
    }
#pragma unroll
    for (int i = 0; i < 4; i++) {
        int row = m0 + ty * 4 + i;
#pragma unroll
        for (int j = 0; j < 4; j++) {
            int gn = n0 + tx * 4 + j;
            float bias = (gn < TT) ? b1[gn] : bo[gn - TT];
            g_P[(size_t)row * PD + gn] = acc[i][j] + bias;
        }
    }
}

// ---- mega-fused: compaction + SDDMM + softmax + SpMM + dense-row stream ---
__global__ __launch_bounds__(256, 6)
void mega_row(const float* __restrict__ A,
              float* __restrict__ outY, float* __restrict__ outA) {
    int i = blockIdx.x;
    __shared__ float  sRow[NN];      // full dense A_soft row (32 KB)
    __shared__ float  sHx[TT];
    __shared__ int    sCols[MAXD];
    __shared__ float  sV[MAXD];      // holds E = exp(sigmoid(p)) per edge
    __shared__ float2 sEdge[MAXD];   // {E, g_P index bits}
    __shared__ float  red[8];
    __shared__ float  accS[128];
    __shared__ float  sDiag, sInv1, sInv2, sDcoef;
    __shared__ int    sCnt;

    int tid = threadIdx.x, warp = tid >> 5, lane = tid & 31;

    // rolling 4-deep prefetch of this warp's A-row chunk (starts DRAM early)
    const float4* rowp = (const float4*)(A + (size_t)i * NN) + warp * 256 + lane;
    float4 vbuf[4];
#pragma unroll
    for (int j = 0; j < 4; j++) vbuf[j] = rowp[j * 32];

    if (tid == 0) { sCnt = 0; sDiag = 0.f; }
    sHx[tid] = g_P[(size_t)i * PD + tid];      // tid < 256 == TT

    // zero the staged dense row
    {
        float4 z = make_float4(0.f, 0.f, 0.f, 0.f);
        float4* sR4 = (float4*)sRow;
#pragma unroll
        for (int c = 0; c < 8; c++) sR4[tid + c * 256] = z;
    }
    __syncthreads();

    // (1) compact A row via ballots: warp w owns cols [w*1024, (w+1)*1024)
#pragma unroll
    for (int c = 0; c < 8; c++) {
        float4 v = vbuf[c & 3];
        if (c < 4) vbuf[c & 3] = rowp[(c + 4) * 32];
        unsigned b0 = __ballot_sync(0xFFFFFFFFu, v.x != 0.f);
        unsigned b1 = __ballot_sync(0xFFFFFFFFu, v.y != 0.f);
        unsigned b2 = __ballot_sync(0xFFFFFFFFu, v.z != 0.f);
        unsigned b3 = __ballot_sync(0xFFFFFFFFu, v.w != 0.f);
        int total = __popc(b0) + __popc(b1) + __popc(b2) + __popc(b3);
        int base = 0;
        if (lane == 0 && total) base = atomicAdd(&sCnt, total);
        base = __shfl_sync(0xFFFFFFFFu, base, 0);
        unsigned lt = (1u << lane) - 1u;
        int col = warp * 1024 + c * 128 + lane * 4;
        int p;
        if (v.x != 0.f) { p = base + __popc(b0 & lt);
                          if (p < MAXD) sCols[p] = col; }
        if (v.y != 0.f) { p = base + __popc(b0) + __popc(b1 & lt);
                          if (p < MAXD) sCols[p] = col + 1; }
        if (v.z != 0.f) { p = base + __popc(b0) + __popc(b1) + __popc(b2 & lt);
                          if (p < MAXD) sCols[p] = col + 2; }
        if (v.w != 0.f) { p = base + __popc(b0) + __popc(b1) + __popc(b2) + __popc(b3 & lt);
                          if (p < MAXD) sCols[p] = col + 3; }
    }
    __syncthreads();
    int deg = min(sCnt, MAXD);

    // (2) SDDMM: warp per edge, 2 edges in flight; E = exp(sigmoid(dot))
    {
        const float4* sHx4 = (const float4*)sHx;
        float4 a0 = sHx4[lane];          // loop-invariant, in registers
        float4 a1 = sHx4[lane + 32];
        for (int k = warp; k < deg; k += 16) {
            int  k2   = k + 8;
            bool has2 = k2 < deg;
            int  c0 = sCols[k];
            int  c1 = sCols[has2 ? k2 : k];
            const float4* hj0 = (const float4*)(g_P + (size_t)c0 * PD);
            const float4* hj1 = (const float4*)(g_P + (size_t)c1 * PD);
            float4 x0 = hj0[lane], x1 = hj0[lane + 32];
            float4 y0 = hj1[lane], y1 = hj1[lane + 32];
            float p0 = a0.x * x0.x + a0.y * x0.y + a0.z * x0.z + a0.w * x0.w
                     + a1.x * x1.x + a1.y * x1.y + a1.z * x1.z + a1.w * x1.w;
            float p1 = a0.x * y0.x + a0.y * y0.y + a0.z * y0.z + a0.w * y0.w
                     + a1.x * y1.x + a1.y * y1.y + a1.z * y1.z + a1.w * y1.w;
#pragma unroll
            for (int d = 16; d; d >>= 1) {
                p0 += __shfl_xor_sync(0xFFFFFFFFu, p0, d);
                p1 += __shfl_xor_sync(0xFFFFFFFFu, p1, d);
            }
            if (lane == 0) {
                sV[k] = __expf(1.f / (1.f + __expf(-p0)));
                if (has2) sV[k2] = __expf(1.f / (1.f + __expf(-p1)));
            }
        }
    }
    __syncthreads();

    // (3) shared softmax sums: exp(v+1)=e*exp(v) -> one sum serves both
    float E = 0.f; int col = -1;
    if (tid < deg) {
        col = sCols[tid];
        E = sV[tid];
        if (col == i) sDiag = E;          // at most one writer
    }
    {
        float s = E;
#pragma unroll
        for (int d = 16; d; d >>= 1) s += __shfl_xor_sync(0xFFFFFFFFu, s, d);
        if (lane == 0) red[warp] = s;
    }
    __syncthreads();
    if (tid == 0) {
        float sum2 = red[0] + red[1] + red[2] + red[3]
                   + red[4] + red[5] + red[6] + red[7];
        float dc   = 1.718281828459045f * sDiag;    // (e-1)*E_diag
        sInv1  = 1.f / (sum2 + dc);
        sInv2  = 1.f / sum2;
        sDcoef = dc;
    }
    __syncthreads();
    if (tid < deg) {
        float E1 = (col == i) ? 2.718281828459045f * E : E;
        sRow[col] = E1 * sInv1;                     // scatter into staged row
        sEdge[tid] = make_float2(E, __int_as_float(col * PD + TT));
    }
    __syncthreads();

    // (4) SpMM single-sum: S[d] = sum_k E_k * HW[col_k][d], unroll x4
    {
        int d   = tid & 127;
        int par = tid >> 7;
        float S = 0.f;
        int k = par;
        for (; k + 6 < deg; k += 8) {
            float2 e0 = sEdge[k],     e1 = sEdge[k + 2];
            float2 e2 = sEdge[k + 4], e3 = sEdge[k + 6];
            float h0 = g_P[__float_as_int(e0.y) + d];
            float h1 = g_P[__float_as_int(e1.y) + d];
            float h2 = g_P[__float_as_int(e2.y) + d];
            float h3 = g_P[__float_as_int(e3.y) + d];
            S += e0.x * h0; S += e1.x * h1; S += e2.x * h2; S += e3.x * h3;
        }
        for (; k < deg; k += 2) {
            float2 e = sEdge[k];
            S += e.x * g_P[__float_as_int(e.y) + d];
        }
        if (par) accS[d] = S;
        __syncthreads();
        if (!par) {
            S += accS[d];
            float hi = g_P[(size_t)i * PD + TT + d];   // diagonal HW row
            float a1 = sInv1 * (S + sDcoef * hi);
            float a2 = sInv2 * S;
            float o1 = a1 >= 0.f ? a1 : 0.01f * a1;
            float o2 = a2 >= 0.f ? a2 : 0.01f * a2;
            outY[(size_t)i * OUTD + d] = o1 + o2;
        }
    }

    // (5) stream the staged dense A_soft row out (coalesced STG.128)
    if (outA) {
        float4* dst = (float4*)(outA + (size_t)i * NN);
        const float4* src = (const float4*)sRow;
#pragma unroll
        for (int c = 0; c < 8; c++) dst[tid + c * 256] = src[tid + c * 256];
    }
}

// ---------------- launch ---------------------------------------------------
extern "C" void kernel_launch(void* const* d_in, const int* in_sizes, int n_in,
                              void* d_out, int out_size) {
    const float* H     = (const float*)d_in[0];
    const float* A     = (const float*)d_in[1];
    const float* gamma = (const float*)d_in[2];
    const float* beta  = (const float*)d_in[3];
    const float* W1    = (const float*)d_in[4];
    const float* b1    = (const float*)d_in[5];
    const float* Wo    = (const float*)d_in[6];
    const float* bo    = (const float*)d_in[7];

    float* outY = (float*)d_out;
    float* outA = nullptr;
    if ((long long)out_size >= (long long)NN * OUTD + (long long)NN * NN)
        outA = (float*)d_out + (size_t)NN * OUTD;

    bn_partial<<<256, 128>>>(H);
    bn_final<<<1, 128>>>(gamma, beta);
    gemm_proj<<<dim3(6, 128), 256>>>(H, W1, b1, Wo, bo);
    mega_row<<<NN, 256>>>(A, outY, outA);
}

// round 5
// speedup vs baseline: 1.2874x; 1.0680x over previous
#include <cuda_runtime.h>
#include <math.h>

#define NN 8192
#define CC 128
#define TT 256
#define PD 384   // TT + OUT
#define OUTD 128
#define MAXD 144 // max row degree (Binomial(8192,0.01): mean 82, max ~116; 144 safe)

// ---------------- scratch (static device globals; no allocations) ----------
__device__ float g_pS[256 * CC];
__device__ float g_pQ[256 * CC];
__device__ float g_s[CC];
__device__ float g_t[CC];
__device__ float g_P[(size_t)NN * PD];          // [Hx | HW] rows, 12.6 MB
__device__ unsigned short g_cols16[(size_t)NN * MAXD];
__device__ int g_deg[NN];

// ---------------- BatchNorm statistics ------------------------------------
__global__ void bn_partial(const float* __restrict__ H) {
    int b = blockIdx.x, c = threadIdx.x;            // 256 blocks x 128 threads
    const float* p = H + (size_t)b * 32 * CC + c;
    float s = 0.f, q = 0.f;
#pragma unroll 8
    for (int r = 0; r < 32; r++) {
        float h = p[(size_t)r * CC];
        s += h; q += h * h;
    }
    g_pS[b * CC + c] = s;
    g_pQ[b * CC + c] = q;
}

__global__ void bn_final(const float* __restrict__ gamma,
                         const float* __restrict__ beta) {
    int c = threadIdx.x;
    float s = 0.f, q = 0.f;
#pragma unroll 8
    for (int b = 0; b < 256; b++) { s += g_pS[b * CC + c]; q += g_pQ[b * CC + c]; }
    float mu  = s / (float)NN;
    float var = q / (float)NN - mu * mu;           // biased variance
    float r   = rsqrtf(var + 1e-5f);
    float sc  = r * gamma[c];
    g_s[c] = sc;
    g_t[c] = beta[c] - mu * sc;
}

// ------- fused prologue: GEMM blocks + adjacency-compaction blocks ---------
// grid = 64 periods x 140 blocks: r<12 -> gemm (768 blocks), else compaction
// (8192 blocks, one row each). Interleaving overlaps compaction's DRAM reads
// with the gemm's FMA work.
__global__ void __launch_bounds__(256)
pre_fused(const float* __restrict__ H,
          const float* __restrict__ A,
          const float* __restrict__ W1,
          const float* __restrict__ b1,
          const float* __restrict__ Wo,
          const float* __restrict__ bo) {
    __shared__ float As[32][65];
    __shared__ float Bs[32][64];
    __shared__ int   cCnt;

    int bid = blockIdx.x;
    int per = bid / 140, r = bid % 140;
    int tid = threadIdx.x;

    if (r >= 12) {
        // ---------------- compaction: one row, 8 warps ----------------
        int i = per * 128 + (r - 12);
        int warp = tid >> 5, lane = tid & 31;
        if (tid == 0) cCnt = 0;
        const float4* rowp = (const float4*)(A + (size_t)i * NN) + warp * 256 + lane;
        float4 vbuf[4];
#pragma unroll
        for (int j = 0; j < 4; j++) vbuf[j] = rowp[j * 32];
        __syncthreads();
        unsigned short* cols = g_cols16 + (size_t)i * MAXD;
#pragma unroll
        for (int c = 0; c < 8; c++) {
            float4 v = vbuf[c & 3];
            if (c < 4) vbuf[c & 3] = rowp[(c + 4) * 32];
            unsigned b0 = __ballot_sync(0xFFFFFFFFu, v.x != 0.f);
            unsigned b1 = __ballot_sync(0xFFFFFFFFu, v.y != 0.f);
            unsigned b2 = __ballot_sync(0xFFFFFFFFu, v.z != 0.f);
            unsigned b3 = __ballot_sync(0xFFFFFFFFu, v.w != 0.f);
            int total = __popc(b0) + __popc(b1) + __popc(b2) + __popc(b3);
            int base = 0;
            if (lane == 0 && total) base = atomicAdd(&cCnt, total);
            base = __shfl_sync(0xFFFFFFFFu, base, 0);
            unsigned lt = (1u << lane) - 1u;
            int col = warp * 1024 + c * 128 + lane * 4;
            int p;
            if (v.x != 0.f) { p = base + __popc(b0 & lt);
                              if (p < MAXD) cols[p] = (unsigned short)col; }
            if (v.y != 0.f) { p = base + __popc(b0) + __popc(b1 & lt);
                              if (p < MAXD) cols[p] = (unsigned short)(col + 1); }
            if (v.z != 0.f) { p = base + __popc(b0) + __popc(b1) + __popc(b2 & lt);
                              if (p < MAXD) cols[p] = (unsigned short)(col + 2); }
            if (v.w != 0.f) { p = base + __popc(b0) + __popc(b1) + __popc(b2) + __popc(b3 & lt);
                              if (p < MAXD) cols[p] = (unsigned short)(col + 3); }
        }
        __syncthreads();
        if (tid == 0) g_deg[i] = min(cCnt, MAXD);
        return;
    }

    // ---------------- GEMM: P = BN(H) @ [W1|Wo] + [b1|bo] ----------------
    int g  = per * 12 + r;          // 0..767
    int m0 = (g / 6) * 64, n0 = (g % 6) * 64;
    int tx = tid & 15, ty = tid >> 4;
    float acc[4][4] = {};

    for (int k0 = 0; k0 < CC; k0 += 32) {
        {
            int kk = tid & 31, rr0 = tid >> 5;
            float sc = g_s[k0 + kk], tt = g_t[k0 + kk];
#pragma unroll
            for (int rr = 0; rr < 64; rr += 8) {
                float h = H[(size_t)(m0 + rr0 + rr) * CC + k0 + kk];
                As[kk][rr0 + rr] = h * sc + tt;
            }
        }
        {
            int n = tid & 63, kb = tid >> 6;
#pragma unroll
            for (int kq = 0; kq < 32; kq += 4) {
                int k = k0 + kq + kb;
                int gn = n0 + n;
                float v = (gn < TT) ? W1[(size_t)k * TT + gn]
                                    : Wo[(size_t)k * CC + (gn - TT)];
                Bs[kq + kb][n] = v;
            }
        }
        __syncthreads();
#pragma unroll
        for (int kk = 0; kk < 32; kk++) {
            float a[4], bb[4];
#pragma unroll
            for (int i = 0; i < 4; i++) a[i] = As[kk][ty * 4 + i];
#pragma unroll
            for (int j = 0; j < 4; j++) bb[j] = Bs[kk][tx * 4 + j];
#pragma unroll
            for (int i = 0; i < 4; i++)
#pragma unroll
                for (int j = 0; j < 4; j++) acc[i][j] += a[i] * bb[j];
        }
        __syncthreads();
    }
#pragma unroll
    for (int i = 0; i < 4; i++) {
        int row = m0 + ty * 4 + i;
#pragma unroll
        for (int j = 0; j < 4; j++) {
            int gn = n0 + tx * 4 + j;
            float bias = (gn < TT) ? b1[gn] : bo[gn - TT];
            g_P[(size_t)row * PD + gn] = acc[i][j] + bias;
        }
    }
}

// ---- mega-fused: SDDMM + softmax + staged dense row (TMA out) + SpMM ------
__global__ __launch_bounds__(256, 6)
void mega_row(float* __restrict__ outY, float* __restrict__ outA) {
    int i = blockIdx.x;
    __shared__ float  sRow[NN];      // full dense A_soft row (32 KB)
    __shared__ float  sHx[TT];
    __shared__ int    sCols[MAXD];
    __shared__ float2 sEdge[MAXD];   // {E, g_P index bits}
    __shared__ float  red[8];
    __shared__ float2 accS[192];     // 3 partitions x 64 dim-pairs
    __shared__ float  sDiag, sInv1, sInv2, sDcoef;

    int tid = threadIdx.x, warp = tid >> 5, lane = tid & 31;
    int deg = g_deg[i];

    // zero the staged dense row
    {
        float4 z = make_float4(0.f, 0.f, 0.f, 0.f);
        float4* sR4 = (float4*)sRow;
#pragma unroll
        for (int c = 0; c < 8; c++) sR4[tid + c * 256] = z;
    }
    if (tid == 0) sDiag = 0.f;
    sHx[tid] = g_P[(size_t)i * PD + tid];      // tid < 256 == TT
    if (tid < deg) sCols[tid] = (int)g_cols16[(size_t)i * MAXD + tid];
    __syncthreads();

    // (1) SDDMM: warp per edge, 2 in flight; sEdge = {exp(sigmoid(dot)), idx}
    {
        const float4* sHx4 = (const float4*)sHx;
        float4 a0 = sHx4[lane];
        float4 a1 = sHx4[lane + 32];
        for (int k = warp; k < deg; k += 16) {
            int  k2   = k + 8;
            bool has2 = k2 < deg;
            int  c0 = sCols[k];
            int  c1 = sCols[has2 ? k2 : k];
            const float4* hj0 = (const float4*)(g_P + (size_t)c0 * PD);
            const float4* hj1 = (const float4*)(g_P + (size_t)c1 * PD);
            float4 x0 = hj0[lane], x1 = hj0[lane + 32];
            float4 y0 = hj1[lane], y1 = hj1[lane + 32];
            float p0 = a0.x * x0.x + a0.y * x0.y + a0.z * x0.z + a0.w * x0.w
                     + a1.x * x1.x + a1.y * x1.y + a1.z * x1.z + a1.w * x1.w;
            float p1 = a0.x * y0.x + a0.y * y0.y + a0.z * y0.z + a0.w * y0.w
                     + a1.x * y1.x + a1.y * y1.y + a1.z * y1.z + a1.w * y1.w;
#pragma unroll
            for (int d = 16; d; d >>= 1) {
                p0 += __shfl_xor_sync(0xFFFFFFFFu, p0, d);
                p1 += __shfl_xor_sync(0xFFFFFFFFu, p1, d);
            }
            if (lane == 0) {
                sEdge[k] = make_float2(__expf(1.f / (1.f + __expf(-p0))),
                                       __int_as_float(c0 * PD + TT));
                if (has2)
                    sEdge[k2] = make_float2(__expf(1.f / (1.f + __expf(-p1))),
                                            __int_as_float(c1 * PD + TT));
            }
        }
    }
    __syncthreads();

    // (2) shared softmax sums: exp(v+1)=e*exp(v) -> one sum serves both
    float E = 0.f; int col = -1;
    if (tid < deg) {
        col = sCols[tid];
        E = sEdge[tid].x;
        if (col == i) sDiag = E;          // at most one writer
    }
    {
        float s = E;
#pragma unroll
        for (int d = 16; d; d >>= 1) s += __shfl_xor_sync(0xFFFFFFFFu, s, d);
        if (lane == 0) red[warp] = s;
    }
    __syncthreads();
    if (tid == 0) {
        float sum2 = red[0] + red[1] + red[2] + red[3]
                   + red[4] + red[5] + red[6] + red[7];
        float dc   = 1.718281828459045f * sDiag;    // (e-1)*E_diag
        sInv1  = 1.f / (sum2 + dc);
        sInv2  = 1.f / sum2;
        sDcoef = dc;
    }
    __syncthreads();
    if (tid < deg) {
        float E1 = (col == i) ? 2.718281828459045f * E : E;
        sRow[col] = E1 * sInv1;                     // scatter into staged row
    }
    __syncthreads();

    // (3) async bulk store of the staged row (overlaps with SpMM below)
    if (outA && tid == 0) {
        unsigned int saddr;
        asm volatile("{ .reg .u64 t; cvta.to.shared.u64 t, %1; cvt.u32.u64 %0, t; }"
                     : "=r"(saddr) : "l"(sRow));
        asm volatile("fence.proxy.async.shared::cta;" ::: "memory");
        asm volatile("cp.async.bulk.global.shared::cta.bulk_group [%0], [%1], %2;"
                     :: "l"(outA + (size_t)i * NN), "r"(saddr), "r"(NN * 4)
                     : "memory");
        asm volatile("cp.async.bulk.commit_group;" ::: "memory");
    }

    // (4) SpMM single-sum, float2 dims: S[d] = sum_k E_k * HW[col_k][d]
    {
        int d2  = tid & 63;        // dim pair {2*d2, 2*d2+1}
        int par = tid >> 6;        // 0..3
        float Sx = 0.f, Sy = 0.f;
        int k = par;
        for (; k + 4 < deg; k += 8) {
            float2 e0 = sEdge[k], e1 = sEdge[k + 4];
            float2 a = *(const float2*)(g_P + __float_as_int(e0.y) + d2 * 2);
            float2 b = *(const float2*)(g_P + __float_as_int(e1.y) + d2 * 2);
            Sx += e0.x * a.x; Sy += e0.x * a.y;
            Sx += e1.x * b.x; Sy += e1.x * b.y;
        }
        for (; k < deg; k += 4) {
            float2 e = sEdge[k];
            float2 a = *(const float2*)(g_P + __float_as_int(e.y) + d2 * 2);
            Sx += e.x * a.x; Sy += e.x * a.y;
        }
        if (par) accS[(par - 1) * 64 + d2] = make_float2(Sx, Sy);
        __syncthreads();
        if (!par) {
            float2 t0 = accS[d2], t1 = accS[64 + d2], t2 = accS[128 + d2];
            Sx += t0.x + t1.x + t2.x;
            Sy += t0.y + t1.y + t2.y;
            float2 hi = *(const float2*)(g_P + (size_t)i * PD + TT + d2 * 2);
            float a1x = sInv1 * (Sx + sDcoef * hi.x), a2x = sInv2 * Sx;
            float a1y = sInv1 * (Sy + sDcoef * hi.y), a2y = sInv2 * Sy;
            float2 o;
            o.x = (a1x >= 0.f ? a1x : 0.01f * a1x) + (a2x >= 0.f ? a2x : 0.01f * a2x);
            o.y = (a1y >= 0.f ? a1y : 0.01f * a1y) + (a2y >= 0.f ? a2y : 0.01f * a2y);
            *(float2*)(outY + (size_t)i * OUTD + d2 * 2) = o;
        }
    }

    // (5) drain the bulk store before CTA exit (smem reuse safety)
    if (outA && tid == 0)
        asm volatile("cp.async.bulk.wait_group.read 0;" ::: "memory");
}

// ---------------- launch ---------------------------------------------------
extern "C" void kernel_launch(void* const* d_in, const int* in_sizes, int n_in,
                              void* d_out, int out_size) {
    const float* H     = (const float*)d_in[0];
    const float* A     = (const float*)d_in[1];
    const float* gamma = (const float*)d_in[2];
    const float* beta  = (const float*)d_in[3];
    const float* W1    = (const float*)d_in[4];
    const float* b1    = (const float*)d_in[5];
    const float* Wo    = (const float*)d_in[6];
    const float* bo    = (const float*)d_in[7];

    float* outY = (float*)d_out;
    float* outA = nullptr;
    if ((long long)out_size >= (long long)NN * OUTD + (long long)NN * NN)
        outA = (float*)d_out + (size_t)NN * OUTD;

    bn_partial<<<256, 128>>>(H);
    bn_final<<<1, 128>>>(gamma, beta);
    pre_fused<<<8960, 256>>>(H, A, W1, b1, Wo, bo);
    mega_row<<<NN, 256>>>(outY, outA);
}